// round 7
// baseline (speedup 1.0000x reference)
#include <cuda_runtime.h>

// Problem constants
#define BB 4
#define NN 4096
#define DD 1024
#define L  16                  // timesteps per chunk
#define V  2                   // d-lanes per thread (float2)
#define C  (NN / L)            // 256 chunks per chain
#define DT 256                 // threads per block
#define NCOL (BB * (DD / (DT * V)))  // 8 chains: (b, d-half)
#define NBLK (C * NCOL)        // 2048 blocks (same as R5)
#define W  16                  // lookback window width
#define D2 (DD / 2)            // row pitch in float2 units

// Scratch: one float4 {A0,S0,A1,S1} per thread per block record.
__device__ float4 g_agg [NBLK * DT];
__device__ float4 g_incl[NBLK * DT];
__device__ int    g_flags[NBLK];   // 0 empty, 1 aggregate ready, 2 inclusive ready

// Plain L2 poll: no acquire, no atomic serialization, not hoistable.
__device__ __forceinline__ int ld_flag_cg(const int* p) {
    int v;
    asm volatile("ld.global.cg.b32 %0, [%1];" : "=r"(v) : "l"(p) : "memory");
    return v;
}

__global__ __launch_bounds__(DT, 3)
void assoc_scan_kernel(const float2* __restrict__ gates,
                       const float2* __restrict__ inputs,
                       float2* __restrict__ out)
{
    const int bx    = blockIdx.x;
    const int chunk = bx >> 3;        // slow-varying -> predecessors scheduled first
    const int col   = bx & 7;         // chain id: (b, d-half)
    const int tid   = threadIdx.x;
    const int b     = col >> 1;
    const int dh    = col & 1;

    // float2-unit offset of (b, t = chunk*L, d-lane pair)
    const int base = (b * NN + chunk * L) * D2 + dh * DT + tid;

    // ---- Load chunk into registers (fully unrolled, coalesced LDG.64) ----
    float2 gv[L], xv[L];
#pragma unroll
    for (int t = 0; t < L; t++) {
        gv[t] = __ldg(gates  + base + t * D2);
        xv[t] = __ldg(inputs + base + t * D2);
    }

    // ---- Local chunk aggregate per lane: (A = prod g, S = scan with h_in=0) ----
    float A0 = 1.0f, S0 = 0.0f, A1 = 1.0f, S1 = 0.0f;
#pragma unroll
    for (int t = 0; t < L; t++) {
        S0 = fmaf(gv[t].x, S0, xv[t].x);  A0 *= gv[t].x;
        S1 = fmaf(gv[t].y, S1, xv[t].y);  A1 *= gv[t].y;
    }

    const int slot = bx * DT + tid;
    float cA0 = 1.0f, cS0 = 0.0f, cA1 = 1.0f, cS1 = 0.0f;  // exclusive carry

    if (chunk == 0) {
        float4 v; v.x = A0; v.y = S0; v.z = A1; v.w = S1;
        __stcg(&g_incl[slot], v);
        __threadfence();
        __syncthreads();
        if (tid == 0) atomicExch(&g_flags[bx], 2);
    } else {
        // Publish aggregate ASAP so successors can make progress.
        float4 v; v.x = A0; v.y = S0; v.z = A1; v.w = S1;
        __stcg(&g_agg[slot], v);
        __threadfence();
        __syncthreads();
        if (tid == 0) atomicExch(&g_flags[bx], 1);

        // ---- Windowed decoupled lookback (W=16 ballot window) ----
        __shared__ int s_take, s_done;
        int k_hi = chunk - 1;
        for (;;) {
            const int Wc = (k_hi + 1 < W) ? (k_hi + 1) : W;
            if (tid < 32) {
                int take, done;
                const unsigned valid = (1u << Wc) - 1u;
                for (;;) {
                    int f = 2;
                    if (tid < Wc) f = ld_flag_cg(&g_flags[(k_hi - tid) * NCOL + col]);
                    unsigned m1 = __ballot_sync(0xffffffffu, f >= 1) & valid;
                    unsigned m2 = __ballot_sync(0xffffffffu, f == 2) & valid;
                    if (m2) {
                        const int s = __ffs(m2) - 1;           // newest inclusive
                        const unsigned need = (1u << s) - 1u;  // newer need aggregates
                        if ((m1 & need) == need) { take = s + 1; done = 1; break; }
                    }
                    if (m1 == valid) { take = Wc; done = 0; break; }
                }
                if (tid == 0) { s_take = take; s_done = done; }
            }
            __syncthreads();
            const int take = s_take;
            const int done = s_done;

            // Fold 'take' predecessors, newest (j=0) to oldest, MLP-4 batches (LDG.128).
            for (int j0 = 0; j0 < take; j0 += 4) {
                const int nb = (take - j0 < 4) ? (take - j0) : 4;
                float4 p0, p1, p2, p3;
                {            const int j = j0;     const float4* s = (done && (j == take-1)) ? g_incl : g_agg;
                             p0 = __ldcg(&s[((k_hi - j) * NCOL + col) * DT + tid]); }
                if (nb > 1) { const int j = j0 + 1; const float4* s = (done && (j == take-1)) ? g_incl : g_agg;
                             p1 = __ldcg(&s[((k_hi - j) * NCOL + col) * DT + tid]); }
                if (nb > 2) { const int j = j0 + 2; const float4* s = (done && (j == take-1)) ? g_incl : g_agg;
                             p2 = __ldcg(&s[((k_hi - j) * NCOL + col) * DT + tid]); }
                if (nb > 3) { const int j = j0 + 3; const float4* s = (done && (j == take-1)) ? g_incl : g_agg;
                             p3 = __ldcg(&s[((k_hi - j) * NCOL + col) * DT + tid]); }

                cS0 = fmaf(cA0, p0.y, cS0); cA0 *= p0.x;  cS1 = fmaf(cA1, p0.w, cS1); cA1 *= p0.z;
                if (nb > 1) { cS0 = fmaf(cA0, p1.y, cS0); cA0 *= p1.x;  cS1 = fmaf(cA1, p1.w, cS1); cA1 *= p1.z; }
                if (nb > 2) { cS0 = fmaf(cA0, p2.y, cS0); cA0 *= p2.x;  cS1 = fmaf(cA1, p2.w, cS1); cA1 *= p2.z; }
                if (nb > 3) { cS0 = fmaf(cA0, p3.y, cS0); cA0 *= p3.x;  cS1 = fmaf(cA1, p3.w, cS1); cA1 *= p3.z; }
            }
            __syncthreads();   // protect s_take/s_done reuse
            if (done) break;
            k_hi -= take;      // chunk 0 always posts inclusive -> guaranteed termination
        }

        // Publish our inclusive prefix: combine(all-predecessors, local)
        float4 inc;
        inc.x = A0 * cA0;  inc.y = fmaf(A0, cS0, S0);
        inc.z = A1 * cA1;  inc.w = fmaf(A1, cS1, S1);
        __stcg(&g_incl[slot], inc);
        __threadfence();
        __syncthreads();
        if (tid == 0) atomicExch(&g_flags[bx], 2);
    }

    // ---- Emit outputs from registers with the carry-in (STG.64) ----
    float h0 = cS0, h1 = cS1;
#pragma unroll
    for (int t = 0; t < L; t++) {
        h0 = fmaf(gv[t].x, h0, xv[t].x);
        h1 = fmaf(gv[t].y, h1, xv[t].y);
        float2 o; o.x = h0; o.y = h1;
        out[base + t * D2] = o;
    }
}

extern "C" void kernel_launch(void* const* d_in, const int* in_sizes, int n_in,
                              void* d_out, int out_size)
{
    const float2* gates  = (const float2*)d_in[0];
    const float2* inputs = (const float2*)d_in[1];
    float2*       out    = (float2*)d_out;

    void* flags_ptr = nullptr;
    cudaGetSymbolAddress(&flags_ptr, g_flags);
    cudaMemsetAsync(flags_ptr, 0, NBLK * sizeof(int));   // reset chain state (captured node)

    assoc_scan_kernel<<<NBLK, DT>>>(gates, inputs, out);
}

// round 8
// speedup vs baseline: 1.2995x; 1.2995x over previous
#include <cuda_runtime.h>

// Problem constants
#define BB 4
#define NN 4096
#define DD 1024
#define L  32                 // timesteps per chunk (R5 optimum)
#define C  (NN / L)           // 128 chunks per chain
#define DT 256                // threads per block = d-tile width
#define NCOL (BB * (DD / DT)) // 16 independent chains
#define NBLK (C * NCOL)       // 2048 blocks
#define W  16                 // lookback window width

// Scratch (static __device__ globals: allowed; no runtime allocation)
__device__ float2 g_agg [NBLK * DT];
__device__ float2 g_incl[NBLK * DT];
__device__ int    g_flags[NBLK];     // 0 = empty, 1 = aggregate ready, 2 = inclusive ready

// Plain L2 poll: no acquire semantics, no atomic serialization, not hoistable.
__device__ __forceinline__ int ld_flag_cg(const int* p) {
    int v;
    asm volatile("ld.global.cg.b32 %0, [%1];" : "=r"(v) : "l"(p) : "memory");
    return v;
}

// Fold 'take' predecessor records (newest j=0 .. oldest), MLP-4 batches.
__device__ __forceinline__ void fold_records(int k_hi, int take, int done, int col, int tid,
                                             float& accA, float& accS)
{
    for (int j0 = 0; j0 < take; j0 += 4) {
        const int nb = (take - j0 < 4) ? (take - j0) : 4;
        float2 p0, p1, p2, p3;
        {            const int j = j0;     const float2* s = (done && (j == take-1)) ? g_incl : g_agg;
                     p0 = __ldcg(&s[((k_hi - j) * NCOL + col) * DT + tid]); }
        if (nb > 1) { const int j = j0 + 1; const float2* s = (done && (j == take-1)) ? g_incl : g_agg;
                     p1 = __ldcg(&s[((k_hi - j) * NCOL + col) * DT + tid]); }
        if (nb > 2) { const int j = j0 + 2; const float2* s = (done && (j == take-1)) ? g_incl : g_agg;
                     p2 = __ldcg(&s[((k_hi - j) * NCOL + col) * DT + tid]); }
        if (nb > 3) { const int j = j0 + 3; const float2* s = (done && (j == take-1)) ? g_incl : g_agg;
                     p3 = __ldcg(&s[((k_hi - j) * NCOL + col) * DT + tid]); }

        accS = fmaf(accA, p0.y, accS); accA *= p0.x;
        if (nb > 1) { accS = fmaf(accA, p1.y, accS); accA *= p1.x; }
        if (nb > 2) { accS = fmaf(accA, p2.y, accS); accA *= p2.x; }
        if (nb > 3) { accS = fmaf(accA, p3.y, accS); accA *= p3.x; }
    }
}

__global__ __launch_bounds__(DT, 3)
void assoc_scan_kernel(const float* __restrict__ gates,
                       const float* __restrict__ inputs,
                       float* __restrict__ out)
{
    const int bx    = blockIdx.x;
    const int chunk = bx >> 4;        // slow-varying -> predecessors scheduled first
    const int col   = bx & 15;        // chain id: (b, d-tile)
    const int tid   = threadIdx.x;

    const int base = ((col >> 2) * NN + chunk * L) * DD + ((col & 3) * DT + tid);

    // ---- Issue chunk loads (fully unrolled, coalesced, high MLP) ----
    float gv[L], xv[L];
#pragma unroll
    for (int t = 0; t < L; t++) {
        gv[t] = __ldg(gates  + base + t * DD);
        xv[t] = __ldg(inputs + base + t * DD);
    }

    const int slot = bx * DT + tid;
    float accA = 1.0f, accS = 0.0f;   // exclusive prefix (carry)
    int   have_carry = (chunk == 0);
    int   k_hi = chunk - 1;

    __shared__ int s_take, s_done, s_ok;

    // ---- Speculative non-blocking lookback: overlap with stream-load latency ----
    // Predecessor aggregates are immutable once flagged, so partial progress is safe.
    if (!have_carry) {
        for (;;) {
            const int Wc = (k_hi + 1 < W) ? (k_hi + 1) : W;
            if (tid < 32) {
                const unsigned valid = (1u << Wc) - 1u;
                int f = 2;
                if (tid < Wc) f = ld_flag_cg(&g_flags[(k_hi - tid) * NCOL + col]);
                unsigned m1 = __ballot_sync(0xffffffffu, f >= 1) & valid;
                unsigned m2 = __ballot_sync(0xffffffffu, f == 2) & valid;
                int take = 0, done = 0, ok = 0;
                if (m2) {
                    const int s = __ffs(m2) - 1;
                    const unsigned need = (1u << s) - 1u;
                    if ((m1 & need) == need) { take = s + 1; done = 1; ok = 1; }
                }
                if (!ok && m1 == valid) { take = Wc; done = 0; ok = 1; }
                if (tid == 0) { s_take = take; s_done = done; s_ok = ok; }
            }
            __syncthreads();
            const int ok = s_ok, take = s_take, done = s_done;
            if (!ok) { __syncthreads(); break; }           // not ready: bail, finish later
            fold_records(k_hi, take, done, col, tid, accA, accS);
            __syncthreads();                                // protect s_* reuse
            if (done) { have_carry = 1; break; }
            k_hi -= take;
        }
    }

    // ---- Local chunk aggregate: (A = prod g, S = scan with h_in = 0) ----
    float A = 1.0f, S = 0.0f;
#pragma unroll
    for (int t = 0; t < L; t++) {
        S = fmaf(gv[t], S, xv[t]);
        A = A * gv[t];
    }

    if (have_carry) {
        // Carry fully known: publish the inclusive directly (skip aggregate publish).
        float2 inc;
        inc.x = A * accA;
        inc.y = fmaf(A, accS, S);
        __stcg(&g_incl[slot], inc);
        __threadfence();
        __syncthreads();
        if (tid == 0) atomicExch(&g_flags[bx], 2);
    } else {
        // Publish aggregate so successors can make progress, then finish lookback.
        float2 v; v.x = A; v.y = S;
        __stcg(&g_agg[slot], v);
        __threadfence();
        __syncthreads();
        if (tid == 0) atomicExch(&g_flags[bx], 1);

        for (;;) {
            const int Wc = (k_hi + 1 < W) ? (k_hi + 1) : W;
            if (tid < 32) {
                int take, done;
                const unsigned valid = (1u << Wc) - 1u;
                for (;;) {
                    int f = 2;
                    if (tid < Wc) f = ld_flag_cg(&g_flags[(k_hi - tid) * NCOL + col]);
                    unsigned m1 = __ballot_sync(0xffffffffu, f >= 1) & valid;
                    unsigned m2 = __ballot_sync(0xffffffffu, f == 2) & valid;
                    if (m2) {
                        const int s = __ffs(m2) - 1;
                        const unsigned need = (1u << s) - 1u;
                        if ((m1 & need) == need) { take = s + 1; done = 1; break; }
                    }
                    if (m1 == valid) { take = Wc; done = 0; break; }
                }
                if (tid == 0) { s_take = take; s_done = done; }
            }
            __syncthreads();
            const int take = s_take, done = s_done;
            fold_records(k_hi, take, done, col, tid, accA, accS);
            __syncthreads();
            if (done) break;
            k_hi -= take;      // chunk 0 always posts inclusive -> guaranteed termination
        }

        float2 inc;
        inc.x = A * accA;
        inc.y = fmaf(A, accS, S);
        __stcg(&g_incl[slot], inc);
        __threadfence();
        __syncthreads();
        if (tid == 0) atomicExch(&g_flags[bx], 2);
    }

    // ---- Emit outputs from registers with the carry-in ----
    float h = accS;
#pragma unroll
    for (int t = 0; t < L; t++) {
        h = fmaf(gv[t], h, xv[t]);
        out[base + t * DD] = h;
    }
}

extern "C" void kernel_launch(void* const* d_in, const int* in_sizes, int n_in,
                              void* d_out, int out_size)
{
    const float* gates  = (const float*)d_in[0];
    const float* inputs = (const float*)d_in[1];
    float*       out    = (float*)d_out;

    void* flags_ptr = nullptr;
    cudaGetSymbolAddress(&flags_ptr, g_flags);
    cudaMemsetAsync(flags_ptr, 0, NBLK * sizeof(int));   // reset chain state (captured node)

    assoc_scan_kernel<<<NBLK, DT>>>(gates, inputs, out);
}

// round 9
// speedup vs baseline: 1.3378x; 1.0294x over previous
#include <cuda_runtime.h>

// Problem constants
#define BB 4
#define NN 4096
#define DD 1024
#define L  32                 // timesteps per chunk (R5 optimum)
#define G  8                  // timesteps per load group (MLP_p1 = 16 LDG)
#define C  (NN / L)           // 128 chunks per chain
#define DT 256                // threads per block = d-tile width
#define NCOL (BB * (DD / DT)) // 16 independent chains
#define NBLK (C * NCOL)       // 2048 blocks
#define W  16                 // lookback window width

// Scratch (static __device__ globals: allowed; no runtime allocation)
__device__ float2 g_agg [NBLK * DT];
__device__ float2 g_incl[NBLK * DT];
__device__ int    g_flags[NBLK];     // 0 = empty, 1 = aggregate ready, 2 = inclusive ready

// Plain L2 poll: no acquire semantics, no atomic serialization, not hoistable.
__device__ __forceinline__ int ld_flag_cg(const int* p) {
    int v;
    asm volatile("ld.global.cg.b32 %0, [%1];" : "=r"(v) : "l"(p) : "memory");
    return v;
}

__global__ __launch_bounds__(DT, 3)
void assoc_scan_kernel(const float* __restrict__ gates,
                       const float* __restrict__ inputs,
                       float* __restrict__ out)
{
    const int bx    = blockIdx.x;
    const int chunk = bx >> 4;        // slow-varying -> predecessors scheduled first
    const int col   = bx & 15;        // chain id: (b, d-tile)
    const int tid   = threadIdx.x;

    const int base = ((col >> 2) * NN + chunk * L) * DD + ((col & 3) * DT + tid);

    // ---- Pipelined load + aggregate: groups of G timesteps.
    // SASS front batch = 16 LDGs (not 64) -> tames cross-CTA L1tex-queue
    // contention (multi-CTA spread), while group g+1 is always in flight
    // before group g is consumed (latency stays hidden).
    float gv[L], xv[L];
    float A = 1.0f, S = 0.0f;

    // group 0 loads
#pragma unroll
    for (int t = 0; t < G; t++) {
        gv[t] = __ldg(gates  + base + t * DD);
        xv[t] = __ldg(inputs + base + t * DD);
    }
    asm volatile("" ::: "memory");    // pin: group 0 loads stay ahead

#pragma unroll
    for (int grp = 1; grp < L / G; grp++) {
        // issue group 'grp' loads
#pragma unroll
        for (int t = grp * G; t < grp * G + G; t++) {
            gv[t] = __ldg(gates  + base + t * DD);
            xv[t] = __ldg(inputs + base + t * DD);
        }
        asm volatile("" ::: "memory");
        // consume group 'grp-1' (waits on its scoreboard; grp already in flight)
#pragma unroll
        for (int t = (grp - 1) * G; t < grp * G; t++) {
            S = fmaf(gv[t], S, xv[t]);
            A = A * gv[t];
        }
        asm volatile("" : "+f"(A), "+f"(S));   // pin FMA placement between load groups
    }
    // consume last group
#pragma unroll
    for (int t = L - G; t < L; t++) {
        S = fmaf(gv[t], S, xv[t]);
        A = A * gv[t];
    }

    const int slot = bx * DT + tid;
    float accA = 1.0f, accS = 0.0f;   // exclusive prefix (carry) for this chunk

    if (chunk == 0) {
        float2 v; v.x = A; v.y = S;
        __stcg(&g_incl[slot], v);
        __threadfence();
        __syncthreads();
        if (tid == 0) atomicExch(&g_flags[bx], 2);
    } else {
        // Publish aggregate ASAP so successors can make progress.
        float2 v; v.x = A; v.y = S;
        __stcg(&g_agg[slot], v);
        __threadfence();
        __syncthreads();
        if (tid == 0) atomicExch(&g_flags[bx], 1);

        // ---- Windowed decoupled lookback (W=16 ballot window) ----
        __shared__ int s_take, s_done;
        int k_hi = chunk - 1;
        for (;;) {
            const int Wc = (k_hi + 1 < W) ? (k_hi + 1) : W;
            if (tid < 32) {
                int take, done;
                const unsigned valid = (1u << Wc) - 1u;
                for (;;) {
                    int f = 2;
                    if (tid < Wc) f = ld_flag_cg(&g_flags[(k_hi - tid) * 16 + col]);
                    unsigned m1 = __ballot_sync(0xffffffffu, f >= 1) & valid;
                    unsigned m2 = __ballot_sync(0xffffffffu, f == 2) & valid;
                    if (m2) {
                        const int s = __ffs(m2) - 1;           // newest inclusive in window
                        const unsigned need = (1u << s) - 1u;  // newer entries need aggregates
                        if ((m1 & need) == need) { take = s + 1; done = 1; break; }
                    }
                    if (m1 == valid) { take = Wc; done = 0; break; }
                }
                if (tid == 0) { s_take = take; s_done = done; }
            }
            __syncthreads();
            const int take = s_take;
            const int done = s_done;

            // Fold 'take' predecessors, newest (j=0) to oldest, MLP-4 batches.
            for (int j0 = 0; j0 < take; j0 += 4) {
                const int nb = (take - j0 < 4) ? (take - j0) : 4;
                float2 p0, p1, p2, p3;
                {            const int j = j0;     const float2* s = (done && (j == take-1)) ? g_incl : g_agg;
                             p0 = __ldcg(&s[((k_hi - j) * 16 + col) * DT + tid]); }
                if (nb > 1) { const int j = j0 + 1; const float2* s = (done && (j == take-1)) ? g_incl : g_agg;
                             p1 = __ldcg(&s[((k_hi - j) * 16 + col) * DT + tid]); }
                if (nb > 2) { const int j = j0 + 2; const float2* s = (done && (j == take-1)) ? g_incl : g_agg;
                             p2 = __ldcg(&s[((k_hi - j) * 16 + col) * DT + tid]); }
                if (nb > 3) { const int j = j0 + 3; const float2* s = (done && (j == take-1)) ? g_incl : g_agg;
                             p3 = __ldcg(&s[((k_hi - j) * 16 + col) * DT + tid]); }

                accS = fmaf(accA, p0.y, accS); accA *= p0.x;
                if (nb > 1) { accS = fmaf(accA, p1.y, accS); accA *= p1.x; }
                if (nb > 2) { accS = fmaf(accA, p2.y, accS); accA *= p2.x; }
                if (nb > 3) { accS = fmaf(accA, p3.y, accS); accA *= p3.x; }
            }
            __syncthreads();   // protect s_take/s_done reuse
            if (done) break;
            k_hi -= take;      // chunk 0 always posts inclusive -> guaranteed termination
        }

        // Publish our inclusive prefix: combine(all-predecessors, local)
        float2 inc;
        inc.x = A * accA;
        inc.y = fmaf(A, accS, S);
        __stcg(&g_incl[slot], inc);
        __threadfence();
        __syncthreads();
        if (tid == 0) atomicExch(&g_flags[bx], 2);
    }

    // ---- Emit outputs from registers with the carry-in ----
    float h = accS;
#pragma unroll
    for (int t = 0; t < L; t++) {
        h = fmaf(gv[t], h, xv[t]);
        out[base + t * DD] = h;
    }
}

extern "C" void kernel_launch(void* const* d_in, const int* in_sizes, int n_in,
                              void* d_out, int out_size)
{
    const float* gates  = (const float*)d_in[0];
    const float* inputs = (const float*)d_in[1];
    float*       out    = (float*)d_out;

    void* flags_ptr = nullptr;
    cudaGetSymbolAddress(&flags_ptr, g_flags);
    cudaMemsetAsync(flags_ptr, 0, NBLK * sizeof(int));   // reset chain state (captured node)

    assoc_scan_kernel<<<NBLK, DT>>>(gates, inputs, out);
}